// round 5
// baseline (speedup 1.0000x reference)
#include <cuda_runtime.h>
#include <cuda_bf16.h>

#define T_STEPS 32768
#define IN_SIZE 1024
#define HID     64
#define GATES   256   // 4 * HID

// Scratch: precomputed input projection, (T, 4H) row-major. 33.5 MB static.
__device__ float g_xproj[T_STEPS * GATES];

// ---------------------------------------------------------------------------
// Kernel 1: x_proj[t][j] = sum_k spec[k][t] * W_ih[j][k] + b_ih[j] + b_hh[j]
// Tiled FP32 GEMM: block = 64 timesteps x 256 gates, BK = 8, 256 threads,
// each thread computes an 8x8 (t x j) micro-tile.
// ---------------------------------------------------------------------------
__global__ void __launch_bounds__(256, 1)
gemm_xproj_kernel(const float* __restrict__ spec,
                  const float* __restrict__ W_ih,
                  const float* __restrict__ b_ih,
                  const float* __restrict__ b_hh)
{
    __shared__ float sS[8][64];    // [kk][t]
    __shared__ float sW[8][GATES]; // [kk][j]

    const int tid = threadIdx.x;
    const int t0  = blockIdx.x * 64;
    const int tj  = (tid & 31) * 8;  // j base (0..248)
    const int tt  = (tid >> 5) * 8;  // t base within tile (0..56)

    float acc[8][8];
#pragma unroll
    for (int i = 0; i < 8; i++)
#pragma unroll
        for (int j = 0; j < 8; j++) acc[i][j] = 0.f;

    const int krow = tid >> 6;   // 0..3
    const int tcol = tid & 63;   // 0..63

    for (int k0 = 0; k0 < IN_SIZE; k0 += 8) {
        sS[krow][tcol]     = spec[(k0 + krow) * T_STEPS + t0 + tcol];
        sS[krow + 4][tcol] = spec[(k0 + krow + 4) * T_STEPS + t0 + tcol];
        float4 wa = *reinterpret_cast<const float4*>(W_ih + (size_t)tid * IN_SIZE + k0);
        float4 wb = *reinterpret_cast<const float4*>(W_ih + (size_t)tid * IN_SIZE + k0 + 4);
        sW[0][tid] = wa.x; sW[1][tid] = wa.y; sW[2][tid] = wa.z; sW[3][tid] = wa.w;
        sW[4][tid] = wb.x; sW[5][tid] = wb.y; sW[6][tid] = wb.z; sW[7][tid] = wb.w;
        __syncthreads();

#pragma unroll
        for (int kk = 0; kk < 8; kk++) {
            float4 s0 = *reinterpret_cast<const float4*>(&sS[kk][tt]);
            float4 s1 = *reinterpret_cast<const float4*>(&sS[kk][tt + 4]);
            float4 w0 = *reinterpret_cast<const float4*>(&sW[kk][tj]);
            float4 w1 = *reinterpret_cast<const float4*>(&sW[kk][tj + 4]);
            float sv[8] = {s0.x, s0.y, s0.z, s0.w, s1.x, s1.y, s1.z, s1.w};
            float wv[8] = {w0.x, w0.y, w0.z, w0.w, w1.x, w1.y, w1.z, w1.w};
#pragma unroll
            for (int i = 0; i < 8; i++)
#pragma unroll
                for (int j = 0; j < 8; j++)
                    acc[i][j] = fmaf(sv[i], wv[j], acc[i][j]);
        }
        __syncthreads();
    }

    float bias[8];
#pragma unroll
    for (int j = 0; j < 8; j++) bias[j] = b_ih[tj + j] + b_hh[tj + j];

#pragma unroll
    for (int i = 0; i < 8; i++) {
        const int t = t0 + tt + i;
        float4 o0, o1;
        o0.x = acc[i][0] + bias[0]; o0.y = acc[i][1] + bias[1];
        o0.z = acc[i][2] + bias[2]; o0.w = acc[i][3] + bias[3];
        o1.x = acc[i][4] + bias[4]; o1.y = acc[i][5] + bias[5];
        o1.z = acc[i][6] + bias[6]; o1.w = acc[i][7] + bias[7];
        *reinterpret_cast<float4*>(&g_xproj[(size_t)t * GATES + tj])     = o0;
        *reinterpret_cast<float4*>(&g_xproj[(size_t)t * GATES + tj + 4]) = o1;
    }
}

// ---------------------------------------------------------------------------
// HW tanh (MUFU.TANH, single op). sigmoid(x) = 0.5 * tanh(0.5 x) + 0.5.
// Validated in R3: rel_err ~4e-7 end-to-end.
// ---------------------------------------------------------------------------
__device__ __forceinline__ float htanh(float x) {
    float r;
    asm("tanh.approx.f32 %0, %1;" : "=f"(r) : "f"(x));
    return r;
}

// Packed f32x2 FMA: acc = a * b + acc
__device__ __forceinline__ void ffma2(unsigned long long& acc,
                                      unsigned long long a,
                                      unsigned long long b) {
    asm("fma.rn.f32x2 %0, %1, %2, %0;" : "+l"(acc) : "l"(a), "l"(b));
}

// Packed add then horizontal sum: returns lo+hi of (a + b)
__device__ __forceinline__ float red2(unsigned long long a,
                                      unsigned long long b) {
    unsigned long long s;
    asm("add.rn.f32x2 %0, %1, %2;" : "=l"(s) : "l"(a), "l"(b));
    float lo, hi;
    asm("mov.b64 {%0, %1}, %2;" : "=f"(lo), "=f"(hi) : "l"(s));
    return lo + hi;
}

// ---------------------------------------------------------------------------
// Kernel 2: sequential LSTM, single block of 512 threads (16 warps, 4/SMSP).
// Thread = (unit u = tid>>3, gate = (tid>>1)&3, khalf = tid&1).
// Each thread computes HALF of one gate row (32 MACs = 16 FFMA2, 8 LDS.128).
// k-halves reduce via shfl.xor(1); the 4 gates of a unit live in one 8-lane
// group -> gather via shfl.xor(2)/(4). One __syncthreads per step,
// double-buffered h. All activations via MUFU.TANH.
// ---------------------------------------------------------------------------
__global__ void __launch_bounds__(512, 1)
lstm_seq_kernel(const float* __restrict__ W_hh, float* __restrict__ out)
{
    __shared__ __align__(16) float h_sh[2][HID];

    const int tid  = threadIdx.x;
    const int u    = tid >> 3;          // unit 0..63
    const int og   = tid & 7;           // offset in 8-lane unit group
    const int gate = og >> 1;           // 0:i 1:f 2:g 3:o
    const int kh   = og & 1;            // k half: 0 -> k[0:32), 1 -> k[32:64)
    const int row  = gate * HID + u;    // W_hh / x_proj row

    // Load this thread's half weight row: 32 floats = 16 packed f32 pairs
    unsigned long long wq[16];
    {
        const ulonglong2* wp = reinterpret_cast<const ulonglong2*>(
            W_hh + (size_t)row * HID + 32 * kh);
#pragma unroll
        for (int i = 0; i < 8; i++) {
            ulonglong2 v = wp[i];
            wq[2 * i] = v.x; wq[2 * i + 1] = v.y;
        }
    }

    // Activation folding: act = q * tanh(m * a) + r
    //   gate 2 (g): tanh   -> (m,q,r) = (1, 1, 0)
    //   others:     sigmoid-> (m,q,r) = (0.5, 0.5, 0.5)
    const float am = (gate == 2) ? 1.f : 0.5f;
    const float aq = am;
    const float ar = (gate == 2) ? 0.f : 0.5f;

    float c = 0.f;
    if (tid < HID) h_sh[0][tid] = 0.f;

    float xn = g_xproj[row];   // t = 0 prefetch (both kh lanes: broadcast)
    __syncthreads();

    for (int t = 0; t < T_STEPS; t++) {
        const int rbuf = t & 1;
        const float xp = xn;
        const int tn = (t + 1 < T_STEPS) ? (t + 1) : t;
        xn = g_xproj[(size_t)tn * GATES + row];   // prefetch next step

        // Half-row matvec: 16 FFMA2 over 4 independent accumulators
        unsigned long long a0 = 0ull, a1 = 0ull, a2 = 0ull, a3 = 0ull;
        const ulonglong2* hp = reinterpret_cast<const ulonglong2*>(
            &h_sh[rbuf][32 * kh]);
#pragma unroll
        for (int k = 0; k < 4; k++) {
            ulonglong2 hA = hp[2 * k];
            ulonglong2 hB = hp[2 * k + 1];
            ffma2(a0, hA.x, wq[4 * k]);
            ffma2(a1, hA.y, wq[4 * k + 1]);
            ffma2(a2, hB.x, wq[4 * k + 2]);
            ffma2(a3, hB.y, wq[4 * k + 3]);
        }
        float s = red2(a0, a1) + red2(a2, a3);
        // Combine k halves (partner lane = lane^1)
        s += __shfl_xor_sync(0xffffffffu, s, 1);
        const float a = xp + s;

        // Own gate activation (1 MUFU op)
        const float v = fmaf(aq, htanh(am * a), ar);

        // Gather all 4 gate activations within the 8-lane group
        const float x2 = __shfl_xor_sync(0xffffffffu, v, 2);   // gate ^ 1
        const float x4 = __shfl_xor_sync(0xffffffffu, v, 4);   // gate ^ 2
        const float x6 = __shfl_xor_sync(0xffffffffu, x2, 4);  // gate ^ 3
        // Map to i,f,g,o by this lane's gate id
        const float gi = (gate == 0) ? v : (gate == 1) ? x2 : (gate == 2) ? x4 : x6;
        const float gf = (gate == 1) ? v : (gate == 0) ? x2 : (gate == 3) ? x4 : x6;
        const float gg = (gate == 2) ? v : (gate == 3) ? x2 : (gate == 0) ? x4 : x6;
        const float go = (gate == 3) ? v : (gate == 2) ? x2 : (gate == 1) ? x4 : x6;

        // All 8 lanes of the group track c redundantly (identical values)
        c = fmaf(gf, c, gi * gg);
        const float th = htanh(c);           // tanh(c), 1 MUFU op
        if (og == 0) h_sh[rbuf ^ 1][u] = go * th;

        __syncthreads();
    }

    // log_softmax over final h (accurate libm; runs once). Final h in buf 0.
    if (tid < HID) {
        const float* hf = h_sh[T_STEPS & 1];
        float m = -1e30f;
#pragma unroll 8
        for (int k = 0; k < HID; k++) m = fmaxf(m, hf[k]);
        float sum = 0.f;
#pragma unroll 8
        for (int k = 0; k < HID; k++) sum += expf(hf[k] - m);
        out[tid] = hf[tid] - m - logf(sum);
    }
}

// ---------------------------------------------------------------------------
// Launch: inputs in metadata order: spectrogram, W_ih, W_hh, b_ih, b_hh
// ---------------------------------------------------------------------------
extern "C" void kernel_launch(void* const* d_in, const int* in_sizes, int n_in,
                              void* d_out, int out_size)
{
    const float* spec = (const float*)d_in[0];
    const float* W_ih = (const float*)d_in[1];
    const float* W_hh = (const float*)d_in[2];
    const float* b_ih = (const float*)d_in[3];
    const float* b_hh = (const float*)d_in[4];
    float* out = (float*)d_out;

    gemm_xproj_kernel<<<T_STEPS / 64, 256>>>(spec, W_ih, b_ih, b_hh);
    lstm_seq_kernel<<<1, 512>>>(W_hh, out);
}

// round 7
// speedup vs baseline: 1.4804x; 1.4804x over previous
#include <cuda_runtime.h>
#include <cuda_bf16.h>

#define T_STEPS 32768
#define IN_SIZE 1024
#define HID     64
#define GATES   256   // 4 * HID

// Scratch: precomputed input projection, (T, 4H) row-major. 33.5 MB static.
__device__ float g_xproj[T_STEPS * GATES];

// ---------------------------------------------------------------------------
// Kernel 1: x_proj[t][j] = sum_k spec[k][t] * W_ih[j][k] + b_ih[j] + b_hh[j]
// Tiled FP32 GEMM: block = 64 timesteps x 256 gates, BK = 8, 256 threads,
// each thread computes an 8x8 (t x j) micro-tile.
// ---------------------------------------------------------------------------
__global__ void __launch_bounds__(256, 1)
gemm_xproj_kernel(const float* __restrict__ spec,
                  const float* __restrict__ W_ih,
                  const float* __restrict__ b_ih,
                  const float* __restrict__ b_hh)
{
    __shared__ float sS[8][64];    // [kk][t]
    __shared__ float sW[8][GATES]; // [kk][j]

    const int tid = threadIdx.x;
    const int t0  = blockIdx.x * 64;
    const int tj  = (tid & 31) * 8;  // j base (0..248)
    const int tt  = (tid >> 5) * 8;  // t base within tile (0..56)

    float acc[8][8];
#pragma unroll
    for (int i = 0; i < 8; i++)
#pragma unroll
        for (int j = 0; j < 8; j++) acc[i][j] = 0.f;

    const int krow = tid >> 6;   // 0..3
    const int tcol = tid & 63;   // 0..63

    for (int k0 = 0; k0 < IN_SIZE; k0 += 8) {
        sS[krow][tcol]     = spec[(k0 + krow) * T_STEPS + t0 + tcol];
        sS[krow + 4][tcol] = spec[(k0 + krow + 4) * T_STEPS + t0 + tcol];
        float4 wa = *reinterpret_cast<const float4*>(W_ih + (size_t)tid * IN_SIZE + k0);
        float4 wb = *reinterpret_cast<const float4*>(W_ih + (size_t)tid * IN_SIZE + k0 + 4);
        sW[0][tid] = wa.x; sW[1][tid] = wa.y; sW[2][tid] = wa.z; sW[3][tid] = wa.w;
        sW[4][tid] = wb.x; sW[5][tid] = wb.y; sW[6][tid] = wb.z; sW[7][tid] = wb.w;
        __syncthreads();

#pragma unroll
        for (int kk = 0; kk < 8; kk++) {
            float4 s0 = *reinterpret_cast<const float4*>(&sS[kk][tt]);
            float4 s1 = *reinterpret_cast<const float4*>(&sS[kk][tt + 4]);
            float4 w0 = *reinterpret_cast<const float4*>(&sW[kk][tj]);
            float4 w1 = *reinterpret_cast<const float4*>(&sW[kk][tj + 4]);
            float sv[8] = {s0.x, s0.y, s0.z, s0.w, s1.x, s1.y, s1.z, s1.w};
            float wv[8] = {w0.x, w0.y, w0.z, w0.w, w1.x, w1.y, w1.z, w1.w};
#pragma unroll
            for (int i = 0; i < 8; i++)
#pragma unroll
                for (int j = 0; j < 8; j++)
                    acc[i][j] = fmaf(sv[i], wv[j], acc[i][j]);
        }
        __syncthreads();
    }

    float bias[8];
#pragma unroll
    for (int j = 0; j < 8; j++) bias[j] = b_ih[tj + j] + b_hh[tj + j];

#pragma unroll
    for (int i = 0; i < 8; i++) {
        const int t = t0 + tt + i;
        float4 o0, o1;
        o0.x = acc[i][0] + bias[0]; o0.y = acc[i][1] + bias[1];
        o0.z = acc[i][2] + bias[2]; o0.w = acc[i][3] + bias[3];
        o1.x = acc[i][4] + bias[4]; o1.y = acc[i][5] + bias[5];
        o1.z = acc[i][6] + bias[6]; o1.w = acc[i][7] + bias[7];
        *reinterpret_cast<float4*>(&g_xproj[(size_t)t * GATES + tj])     = o0;
        *reinterpret_cast<float4*>(&g_xproj[(size_t)t * GATES + tj + 4]) = o1;
    }
}

// ---------------------------------------------------------------------------
// HW tanh (MUFU.TANH, single op, lat ~16). sigmoid(x) = 0.5*tanh(0.5x)+0.5.
// Validated R3/R5: end-to-end rel_err ~4e-7.
// ---------------------------------------------------------------------------
__device__ __forceinline__ float htanh(float x) {
    float r;
    asm("tanh.approx.f32 %0, %1;" : "=f"(r) : "f"(x));
    return r;
}

// Packed f32x2 FMA: acc = a * b + acc
__device__ __forceinline__ void ffma2(unsigned long long& acc,
                                      unsigned long long a,
                                      unsigned long long b) {
    asm("fma.rn.f32x2 %0, %1, %2, %0;" : "+l"(acc) : "l"(a), "l"(b));
}
__device__ __forceinline__ float2 unpack2(unsigned long long v) {
    float2 r;
    asm("mov.b64 {%0, %1}, %2;" : "=f"(r.x), "=f"(r.y) : "l"(v));
    return r;
}

// ---------------------------------------------------------------------------
// Kernel 2: sequential LSTM, single block of 256 threads (8 warps, 2/SMSP —
// the empirically optimal width; R3=4w and R5=16w both regressed).
// EXACT R2 structure: thread = (unit u = tid>>2, gate = tid&3), full
// 64-weight gate row per thread (32 FFMA2), 4-lane shfl.idx gate exchange,
// double-buffered h, one __syncthreads per step.
// Single change vs R2: activations via MUFU.TANH (1 op each).
// ---------------------------------------------------------------------------
__global__ void __launch_bounds__(256, 1)
lstm_seq_kernel(const float* __restrict__ W_hh, float* __restrict__ out)
{
    __shared__ __align__(16) float h_sh[2][HID];

    const int tid  = threadIdx.x;
    const int u    = tid >> 2;        // hidden unit 0..63
    const int gate = tid & 3;         // 0:i 1:f 2:g 3:o
    const int lane = tid & 31;
    const int lbase = lane & ~3;      // first lane of this unit's 4-lane group
    const int row  = gate * HID + u;  // W_hh / x_proj row for this thread

    // Load weight row as 32 packed f32 pairs (64 regs)
    unsigned long long wq[HID / 2];
    {
        const ulonglong2* wp =
            reinterpret_cast<const ulonglong2*>(W_hh + (size_t)row * HID);
#pragma unroll
        for (int i = 0; i < HID / 8; i++) {       // 8 x ulonglong2 = 64 floats
            ulonglong2 v0 = wp[2 * i];
            ulonglong2 v1 = wp[2 * i + 1];
            wq[4 * i]     = v0.x; wq[4 * i + 1] = v0.y;
            wq[4 * i + 2] = v1.x; wq[4 * i + 3] = v1.y;
        }
    }

    // Activation folding: act = q * tanh(m * a) + r
    //   gate 2 (g): tanh    -> (1, 1, 0)
    //   others:     sigmoid -> (0.5, 0.5, 0.5)
    const float am = (gate == 2) ? 1.f : 0.5f;
    const float aq = am;
    const float ar = (gate == 2) ? 0.f : 0.5f;

    float c = 0.f;
    if (tid < HID) h_sh[0][tid] = 0.f;

    float xn = g_xproj[row];  // x_proj for t = 0
    __syncthreads();

    for (int t = 0; t < T_STEPS; t++) {
        const int rbuf = t & 1;
        const float xc = xn;
        const int tn = (t + 1 < T_STEPS) ? (t + 1) : t;
        xn = g_xproj[(size_t)tn * GATES + row];   // prefetch next step

        // a = x_proj + h . W_hh[row]  (packed FFMA2, 32 instructions)
        unsigned long long a0 = 0ull, a1 = 0ull, a2 = 0ull, a3 = 0ull;
        const ulonglong2* hp =
            reinterpret_cast<const ulonglong2*>(&h_sh[rbuf][0]);
#pragma unroll
        for (int k = 0; k < HID / 8; k++) {       // 8 iterations
            ulonglong2 hA = hp[2 * k];
            ulonglong2 hB = hp[2 * k + 1];
            ffma2(a0, hA.x, wq[4 * k]);
            ffma2(a1, hA.y, wq[4 * k + 1]);
            ffma2(a2, hB.x, wq[4 * k + 2]);
            ffma2(a3, hB.y, wq[4 * k + 3]);
        }
        float2 f0 = unpack2(a0), f1 = unpack2(a1);
        float2 f2 = unpack2(a2), f3 = unpack2(a3);
        const float a = xc + (((f0.x + f0.y) + (f1.x + f1.y)) +
                              ((f2.x + f2.y) + (f3.x + f3.y)));

        // Own gate activation: 1 MUFU.TANH op
        const float act = fmaf(aq, htanh(am * a), ar);

        // Exchange the 4 gate activations within the 4-lane group
        const float i_a = __shfl_sync(0xffffffffu, act, lbase + 0);
        const float f_a = __shfl_sync(0xffffffffu, act, lbase + 1);
        const float g_a = __shfl_sync(0xffffffffu, act, lbase + 2);
        const float o_a = __shfl_sync(0xffffffffu, act, lbase + 3);

        // All 4 lanes of the group redundantly update c and h (identical)
        c = fmaf(f_a, c, i_a * g_a);
        const float th = htanh(c);               // tanh(c), 1 MUFU op
        if (gate == 0) h_sh[rbuf ^ 1][u] = o_a * th;

        __syncthreads();
    }

    // log_softmax over final h (accurate libm; runs once). Final h in buf 0.
    if (tid < HID) {
        const float* hf = h_sh[T_STEPS & 1];
        float m = -1e30f;
#pragma unroll 8
        for (int k = 0; k < HID; k++) m = fmaxf(m, hf[k]);
        float sum = 0.f;
#pragma unroll 8
        for (int k = 0; k < HID; k++) sum += expf(hf[k] - m);
        out[tid] = hf[tid] - m - logf(sum);
    }
}

// ---------------------------------------------------------------------------
// Launch: inputs in metadata order: spectrogram, W_ih, W_hh, b_ih, b_hh
// ---------------------------------------------------------------------------
extern "C" void kernel_launch(void* const* d_in, const int* in_sizes, int n_in,
                              void* d_out, int out_size)
{
    const float* spec = (const float*)d_in[0];
    const float* W_ih = (const float*)d_in[1];
    const float* W_hh = (const float*)d_in[2];
    const float* b_ih = (const float*)d_in[3];
    const float* b_hh = (const float*)d_in[4];
    float* out = (float*)d_out;

    gemm_xproj_kernel<<<T_STEPS / 64, 256>>>(spec, W_ih, b_ih, b_hh);
    lstm_seq_kernel<<<1, 256>>>(W_hh, out);
}

// round 8
// speedup vs baseline: 1.8051x; 1.2194x over previous
#include <cuda_runtime.h>
#include <cuda_bf16.h>

#define T_STEPS 32768
#define IN_SIZE 1024
#define HID     64
#define GATES   256   // 4 * HID

// Scratch: precomputed input projection, (T, 4H) row-major. 33.5 MB static.
__device__ float g_xproj[T_STEPS * GATES];

// ---------------------------------------------------------------------------
// Kernel 1: x_proj[t][j] = sum_k spec[k][t] * W_ih[j][k] + b_ih[j] + b_hh[j]
// Tiled FP32 GEMM: block = 64 timesteps x 256 gates, BK = 8, 256 threads,
// each thread computes an 8x8 (t x j) micro-tile.
// ---------------------------------------------------------------------------
__global__ void __launch_bounds__(256, 1)
gemm_xproj_kernel(const float* __restrict__ spec,
                  const float* __restrict__ W_ih,
                  const float* __restrict__ b_ih,
                  const float* __restrict__ b_hh)
{
    __shared__ float sS[8][64];    // [kk][t]
    __shared__ float sW[8][GATES]; // [kk][j]

    const int tid = threadIdx.x;
    const int t0  = blockIdx.x * 64;
    const int tj  = (tid & 31) * 8;  // j base (0..248)
    const int tt  = (tid >> 5) * 8;  // t base within tile (0..56)

    float acc[8][8];
#pragma unroll
    for (int i = 0; i < 8; i++)
#pragma unroll
        for (int j = 0; j < 8; j++) acc[i][j] = 0.f;

    const int krow = tid >> 6;   // 0..3
    const int tcol = tid & 63;   // 0..63

    for (int k0 = 0; k0 < IN_SIZE; k0 += 8) {
        sS[krow][tcol]     = spec[(k0 + krow) * T_STEPS + t0 + tcol];
        sS[krow + 4][tcol] = spec[(k0 + krow + 4) * T_STEPS + t0 + tcol];
        float4 wa = *reinterpret_cast<const float4*>(W_ih + (size_t)tid * IN_SIZE + k0);
        float4 wb = *reinterpret_cast<const float4*>(W_ih + (size_t)tid * IN_SIZE + k0 + 4);
        sW[0][tid] = wa.x; sW[1][tid] = wa.y; sW[2][tid] = wa.z; sW[3][tid] = wa.w;
        sW[4][tid] = wb.x; sW[5][tid] = wb.y; sW[6][tid] = wb.z; sW[7][tid] = wb.w;
        __syncthreads();

#pragma unroll
        for (int kk = 0; kk < 8; kk++) {
            float4 s0 = *reinterpret_cast<const float4*>(&sS[kk][tt]);
            float4 s1 = *reinterpret_cast<const float4*>(&sS[kk][tt + 4]);
            float4 w0 = *reinterpret_cast<const float4*>(&sW[kk][tj]);
            float4 w1 = *reinterpret_cast<const float4*>(&sW[kk][tj + 4]);
            float sv[8] = {s0.x, s0.y, s0.z, s0.w, s1.x, s1.y, s1.z, s1.w};
            float wv[8] = {w0.x, w0.y, w0.z, w0.w, w1.x, w1.y, w1.z, w1.w};
#pragma unroll
            for (int i = 0; i < 8; i++)
#pragma unroll
                for (int j = 0; j < 8; j++)
                    acc[i][j] = fmaf(sv[i], wv[j], acc[i][j]);
        }
        __syncthreads();
    }

    float bias[8];
#pragma unroll
    for (int j = 0; j < 8; j++) bias[j] = b_ih[tj + j] + b_hh[tj + j];

#pragma unroll
    for (int i = 0; i < 8; i++) {
        const int t = t0 + tt + i;
        float4 o0, o1;
        o0.x = acc[i][0] + bias[0]; o0.y = acc[i][1] + bias[1];
        o0.z = acc[i][2] + bias[2]; o0.w = acc[i][3] + bias[3];
        o1.x = acc[i][4] + bias[4]; o1.y = acc[i][5] + bias[5];
        o1.z = acc[i][6] + bias[6]; o1.w = acc[i][7] + bias[7];
        *reinterpret_cast<float4*>(&g_xproj[(size_t)t * GATES + tj])     = o0;
        *reinterpret_cast<float4*>(&g_xproj[(size_t)t * GATES + tj + 4]) = o1;
    }
}

// ---------------------------------------------------------------------------
// HW tanh (MUFU.TANH, single op, lat ~16). sigmoid(x) = 0.5*tanh(0.5x)+0.5.
// ---------------------------------------------------------------------------
__device__ __forceinline__ float htanh(float x) {
    float r;
    asm("tanh.approx.f32 %0, %1;" : "=f"(r) : "f"(x));
    return r;
}

// Packed f32x2 FMA: acc = a * b + acc
__device__ __forceinline__ void ffma2(unsigned long long& acc,
                                      unsigned long long a,
                                      unsigned long long b) {
    asm("fma.rn.f32x2 %0, %1, %2, %0;" : "+l"(acc) : "l"(a), "l"(b));
}
__device__ __forceinline__ float2 unpack2(unsigned long long v) {
    float2 r;
    asm("mov.b64 {%0, %1}, %2;" : "=f"(r.x), "=f"(r.y) : "l"(v));
    return r;
}

// ---------------------------------------------------------------------------
// Kernel 2: sequential LSTM, single block of 256 threads (8 warps, 2/SMSP).
// Thread = (unit u = tid>>2, gate = tid&3). Full 64-weight gate row per
// thread (32 FFMA2), 4-lane shfl gate exchange, double-buffered h, one
// __syncthreads per step, MUFU.TANH activations.
// R8 change: xproj prefetched FOUR steps ahead via a register ring
// (LDG DRAM latency ~577cyc is fully covered by 4 steps), loop unrolled 4x.
// ---------------------------------------------------------------------------
__global__ void __launch_bounds__(256, 1)
lstm_seq_kernel(const float* __restrict__ W_hh, float* __restrict__ out)
{
    __shared__ __align__(16) float h_sh[2][HID];

    const int tid  = threadIdx.x;
    const int u    = tid >> 2;        // hidden unit 0..63
    const int gate = tid & 3;         // 0:i 1:f 2:g 3:o
    const int lane = tid & 31;
    const int lbase = lane & ~3;      // first lane of this unit's 4-lane group
    const int row  = gate * HID + u;  // W_hh / x_proj row for this thread

    // Load weight row as 32 packed f32 pairs (64 regs)
    unsigned long long wq[HID / 2];
    {
        const ulonglong2* wp =
            reinterpret_cast<const ulonglong2*>(W_hh + (size_t)row * HID);
#pragma unroll
        for (int i = 0; i < HID / 8; i++) {
            ulonglong2 v0 = wp[2 * i];
            ulonglong2 v1 = wp[2 * i + 1];
            wq[4 * i]     = v0.x; wq[4 * i + 1] = v0.y;
            wq[4 * i + 2] = v1.x; wq[4 * i + 3] = v1.y;
        }
    }

    // Activation folding: act = q * tanh(m * a) + r
    const float am = (gate == 2) ? 1.f : 0.5f;
    const float aq = am;
    const float ar = (gate == 2) ? 0.f : 0.5f;

    float c = 0.f;
    if (tid < HID) h_sh[0][tid] = 0.f;

    // Depth-4 xproj prefetch ring: xf[s] holds x_proj[t + s][row]
    float xf0 = g_xproj[0 * GATES + row];
    float xf1 = g_xproj[1 * GATES + row];
    float xf2 = g_xproj[2 * GATES + row];
    float xf3 = g_xproj[3 * GATES + row];
    __syncthreads();

#define LSTM_STEP(XSLOT, RBUF, TNEXT)                                        \
    {                                                                        \
        const float xc = XSLOT;                                              \
        const int tld = ((TNEXT) < T_STEPS) ? (TNEXT) : (T_STEPS - 1);       \
        XSLOT = g_xproj[(size_t)tld * GATES + row];  /* 4 steps ahead */     \
        unsigned long long a0 = 0ull, a1 = 0ull, a2 = 0ull, a3 = 0ull;       \
        const ulonglong2* hp =                                               \
            reinterpret_cast<const ulonglong2*>(&h_sh[(RBUF)][0]);           \
        _Pragma("unroll")                                                    \
        for (int k = 0; k < HID / 8; k++) {                                  \
            ulonglong2 hA = hp[2 * k];                                       \
            ulonglong2 hB = hp[2 * k + 1];                                   \
            ffma2(a0, hA.x, wq[4 * k]);                                      \
            ffma2(a1, hA.y, wq[4 * k + 1]);                                  \
            ffma2(a2, hB.x, wq[4 * k + 2]);                                  \
            ffma2(a3, hB.y, wq[4 * k + 3]);                                  \
        }                                                                    \
        float2 f0 = unpack2(a0), f1 = unpack2(a1);                           \
        float2 f2 = unpack2(a2), f3 = unpack2(a3);                           \
        const float a = xc + (((f0.x + f0.y) + (f1.x + f1.y)) +              \
                              ((f2.x + f2.y) + (f3.x + f3.y)));              \
        const float act = fmaf(aq, htanh(am * a), ar);                       \
        const float i_a = __shfl_sync(0xffffffffu, act, lbase + 0);          \
        const float f_a = __shfl_sync(0xffffffffu, act, lbase + 1);          \
        const float g_a = __shfl_sync(0xffffffffu, act, lbase + 2);          \
        const float o_a = __shfl_sync(0xffffffffu, act, lbase + 3);          \
        c = fmaf(f_a, c, i_a * g_a);                                         \
        const float th = htanh(c);                                           \
        if (gate == 0) h_sh[(RBUF) ^ 1][u] = o_a * th;                       \
        __syncthreads();                                                     \
    }

    for (int t = 0; t < T_STEPS; t += 4) {
        LSTM_STEP(xf0, 0, t + 4);
        LSTM_STEP(xf1, 1, t + 5);
        LSTM_STEP(xf2, 0, t + 6);
        LSTM_STEP(xf3, 1, t + 7);
    }
#undef LSTM_STEP

    // log_softmax over final h (accurate libm; runs once). Final h in buf 0.
    if (tid < HID) {
        const float* hf = h_sh[T_STEPS & 1];
        float m = -1e30f;
#pragma unroll 8
        for (int k = 0; k < HID; k++) m = fmaxf(m, hf[k]);
        float sum = 0.f;
#pragma unroll 8
        for (int k = 0; k < HID; k++) sum += expf(hf[k] - m);
        out[tid] = hf[tid] - m - logf(sum);
    }
}

// ---------------------------------------------------------------------------
// Launch: inputs in metadata order: spectrogram, W_ih, W_hh, b_ih, b_hh
// ---------------------------------------------------------------------------
extern "C" void kernel_launch(void* const* d_in, const int* in_sizes, int n_in,
                              void* d_out, int out_size)
{
    const float* spec = (const float*)d_in[0];
    const float* W_ih = (const float*)d_in[1];
    const float* W_hh = (const float*)d_in[2];
    const float* b_ih = (const float*)d_in[3];
    const float* b_hh = (const float*)d_in[4];
    float* out = (float*)d_out;

    gemm_xproj_kernel<<<T_STEPS / 64, 256>>>(spec, W_ih, b_ih, b_hh);
    lstm_seq_kernel<<<1, 256>>>(W_hh, out);
}

// round 9
// speedup vs baseline: 1.8735x; 1.0379x over previous
#include <cuda_runtime.h>
#include <cuda_bf16.h>

#define T_STEPS 32768
#define IN_SIZE 1024
#define HID     64
#define GATES   256   // 4 * HID

// Scratch: precomputed input projection, (T, 4H) row-major. 33.5 MB static.
__device__ float g_xproj[T_STEPS * GATES];

// ---------------------------------------------------------------------------
// Kernel 1: x_proj[t][j] = sum_k spec[k][t] * W_ih[j][k] + b_ih[j] + b_hh[j]
// Tiled FP32 GEMM: block = 64 timesteps x 256 gates, BK = 8, 256 threads,
// each thread computes an 8x8 (t x j) micro-tile.
// ---------------------------------------------------------------------------
__global__ void __launch_bounds__(256, 1)
gemm_xproj_kernel(const float* __restrict__ spec,
                  const float* __restrict__ W_ih,
                  const float* __restrict__ b_ih,
                  const float* __restrict__ b_hh)
{
    __shared__ float sS[8][64];    // [kk][t]
    __shared__ float sW[8][GATES]; // [kk][j]

    const int tid = threadIdx.x;
    const int t0  = blockIdx.x * 64;
    const int tj  = (tid & 31) * 8;  // j base (0..248)
    const int tt  = (tid >> 5) * 8;  // t base within tile (0..56)

    float acc[8][8];
#pragma unroll
    for (int i = 0; i < 8; i++)
#pragma unroll
        for (int j = 0; j < 8; j++) acc[i][j] = 0.f;

    const int krow = tid >> 6;   // 0..3
    const int tcol = tid & 63;   // 0..63

    for (int k0 = 0; k0 < IN_SIZE; k0 += 8) {
        sS[krow][tcol]     = spec[(k0 + krow) * T_STEPS + t0 + tcol];
        sS[krow + 4][tcol] = spec[(k0 + krow + 4) * T_STEPS + t0 + tcol];
        float4 wa = *reinterpret_cast<const float4*>(W_ih + (size_t)tid * IN_SIZE + k0);
        float4 wb = *reinterpret_cast<const float4*>(W_ih + (size_t)tid * IN_SIZE + k0 + 4);
        sW[0][tid] = wa.x; sW[1][tid] = wa.y; sW[2][tid] = wa.z; sW[3][tid] = wa.w;
        sW[4][tid] = wb.x; sW[5][tid] = wb.y; sW[6][tid] = wb.z; sW[7][tid] = wb.w;
        __syncthreads();

#pragma unroll
        for (int kk = 0; kk < 8; kk++) {
            float4 s0 = *reinterpret_cast<const float4*>(&sS[kk][tt]);
            float4 s1 = *reinterpret_cast<const float4*>(&sS[kk][tt + 4]);
            float4 w0 = *reinterpret_cast<const float4*>(&sW[kk][tj]);
            float4 w1 = *reinterpret_cast<const float4*>(&sW[kk][tj + 4]);
            float sv[8] = {s0.x, s0.y, s0.z, s0.w, s1.x, s1.y, s1.z, s1.w};
            float wv[8] = {w0.x, w0.y, w0.z, w0.w, w1.x, w1.y, w1.z, w1.w};
#pragma unroll
            for (int i = 0; i < 8; i++)
#pragma unroll
                for (int j = 0; j < 8; j++)
                    acc[i][j] = fmaf(sv[i], wv[j], acc[i][j]);
        }
        __syncthreads();
    }

    float bias[8];
#pragma unroll
    for (int j = 0; j < 8; j++) bias[j] = b_ih[tj + j] + b_hh[tj + j];

#pragma unroll
    for (int i = 0; i < 8; i++) {
        const int t = t0 + tt + i;
        float4 o0, o1;
        o0.x = acc[i][0] + bias[0]; o0.y = acc[i][1] + bias[1];
        o0.z = acc[i][2] + bias[2]; o0.w = acc[i][3] + bias[3];
        o1.x = acc[i][4] + bias[4]; o1.y = acc[i][5] + bias[5];
        o1.z = acc[i][6] + bias[6]; o1.w = acc[i][7] + bias[7];
        *reinterpret_cast<float4*>(&g_xproj[(size_t)t * GATES + tj])     = o0;
        *reinterpret_cast<float4*>(&g_xproj[(size_t)t * GATES + tj + 4]) = o1;
    }
}

// ---------------------------------------------------------------------------
// HW tanh (MUFU.TANH, single op, lat ~16). sigmoid(x) = 0.5*tanh(0.5x)+0.5.
// ---------------------------------------------------------------------------
__device__ __forceinline__ float htanh(float x) {
    float r;
    asm("tanh.approx.f32 %0, %1;" : "=f"(r) : "f"(x));
    return r;
}

// Packed f32x2 FMA: acc = a * b + acc
__device__ __forceinline__ void ffma2(unsigned long long& acc,
                                      unsigned long long a,
                                      unsigned long long b) {
    asm("fma.rn.f32x2 %0, %1, %2, %0;" : "+l"(acc) : "l"(a), "l"(b));
}
// Packed add: r = a + b (componentwise)
__device__ __forceinline__ unsigned long long fadd2(unsigned long long a,
                                                    unsigned long long b) {
    unsigned long long r;
    asm("add.rn.f32x2 %0, %1, %2;" : "=l"(r) : "l"(a), "l"(b));
    return r;
}
__device__ __forceinline__ float2 unpack2(unsigned long long v) {
    float2 r;
    asm("mov.b64 {%0, %1}, %2;" : "=f"(r.x), "=f"(r.y) : "l"(v));
    return r;
}

// ---------------------------------------------------------------------------
// Kernel 2: sequential LSTM, single block of 256 threads (8 warps, 2/SMSP).
// Thread = (unit u = tid>>2, gate = tid&3). Full 64-weight gate row per
// thread (32 FFMA2), 4-lane shfl gate exchange, double-buffered h, one
// __syncthreads per step, MUFU.TANH activations.
// R9 change: xproj prefetch ring deepened 4 -> 8 (MLP=8 cuts the exposed
// DRAM latency per step to ~72cyc), loop unrolled 8x; packed reduce tree.
// ---------------------------------------------------------------------------
__global__ void __launch_bounds__(256, 1)
lstm_seq_kernel(const float* __restrict__ W_hh, float* __restrict__ out)
{
    __shared__ __align__(16) float h_sh[2][HID];

    const int tid  = threadIdx.x;
    const int u    = tid >> 2;        // hidden unit 0..63
    const int gate = tid & 3;         // 0:i 1:f 2:g 3:o
    const int lane = tid & 31;
    const int lbase = lane & ~3;      // first lane of this unit's 4-lane group
    const int row  = gate * HID + u;  // W_hh / x_proj row for this thread

    // Load weight row as 32 packed f32 pairs (64 regs)
    unsigned long long wq[HID / 2];
    {
        const ulonglong2* wp =
            reinterpret_cast<const ulonglong2*>(W_hh + (size_t)row * HID);
#pragma unroll
        for (int i = 0; i < HID / 8; i++) {
            ulonglong2 v0 = wp[2 * i];
            ulonglong2 v1 = wp[2 * i + 1];
            wq[4 * i]     = v0.x; wq[4 * i + 1] = v0.y;
            wq[4 * i + 2] = v1.x; wq[4 * i + 3] = v1.y;
        }
    }

    // Activation folding: act = q * tanh(m * a) + r
    const float am = (gate == 2) ? 1.f : 0.5f;
    const float aq = am;
    const float ar = (gate == 2) ? 0.f : 0.5f;

    float c = 0.f;
    if (tid < HID) h_sh[0][tid] = 0.f;

    // Depth-8 xproj prefetch ring: xf[s] holds x_proj[t + s][row]
    float xf0 = g_xproj[0 * GATES + row];
    float xf1 = g_xproj[1 * GATES + row];
    float xf2 = g_xproj[2 * GATES + row];
    float xf3 = g_xproj[3 * GATES + row];
    float xf4 = g_xproj[4 * GATES + row];
    float xf5 = g_xproj[5 * GATES + row];
    float xf6 = g_xproj[6 * GATES + row];
    float xf7 = g_xproj[7 * GATES + row];
    __syncthreads();

#define LSTM_STEP(XSLOT, RBUF, TNEXT)                                        \
    {                                                                        \
        const float xc = XSLOT;                                              \
        const int tld = ((TNEXT) < T_STEPS) ? (TNEXT) : (T_STEPS - 1);       \
        XSLOT = g_xproj[(size_t)tld * GATES + row];  /* 8 steps ahead */     \
        unsigned long long a0 = 0ull, a1 = 0ull, a2 = 0ull, a3 = 0ull;       \
        const ulonglong2* hp =                                               \
            reinterpret_cast<const ulonglong2*>(&h_sh[(RBUF)][0]);           \
        _Pragma("unroll")                                                    \
        for (int k = 0; k < HID / 8; k++) {                                  \
            ulonglong2 hA = hp[2 * k];                                       \
            ulonglong2 hB = hp[2 * k + 1];                                   \
            ffma2(a0, hA.x, wq[4 * k]);                                      \
            ffma2(a1, hA.y, wq[4 * k + 1]);                                  \
            ffma2(a2, hB.x, wq[4 * k + 2]);                                  \
            ffma2(a3, hB.y, wq[4 * k + 3]);                                  \
        }                                                                    \
        float2 fs = unpack2(fadd2(fadd2(a0, a1), fadd2(a2, a3)));            \
        const float a = xc + (fs.x + fs.y);                                  \
        const float act = fmaf(aq, htanh(am * a), ar);                       \
        const float i_a = __shfl_sync(0xffffffffu, act, lbase + 0);          \
        const float f_a = __shfl_sync(0xffffffffu, act, lbase + 1);          \
        const float g_a = __shfl_sync(0xffffffffu, act, lbase + 2);          \
        const float o_a = __shfl_sync(0xffffffffu, act, lbase + 3);          \
        c = fmaf(f_a, c, i_a * g_a);                                         \
        const float th = htanh(c);                                           \
        if (gate == 0) h_sh[(RBUF) ^ 1][u] = o_a * th;                       \
        __syncthreads();                                                     \
    }

    for (int t = 0; t < T_STEPS; t += 8) {
        LSTM_STEP(xf0, 0, t + 8);
        LSTM_STEP(xf1, 1, t + 9);
        LSTM_STEP(xf2, 0, t + 10);
        LSTM_STEP(xf3, 1, t + 11);
        LSTM_STEP(xf4, 0, t + 12);
        LSTM_STEP(xf5, 1, t + 13);
        LSTM_STEP(xf6, 0, t + 14);
        LSTM_STEP(xf7, 1, t + 15);
    }
#undef LSTM_STEP

    // log_softmax over final h (accurate libm; runs once). Final h in buf 0.
    if (tid < HID) {
        const float* hf = h_sh[T_STEPS & 1];
        float m = -1e30f;
#pragma unroll 8
        for (int k = 0; k < HID; k++) m = fmaxf(m, hf[k]);
        float sum = 0.f;
#pragma unroll 8
        for (int k = 0; k < HID; k++) sum += expf(hf[k] - m);
        out[tid] = hf[tid] - m - logf(sum);
    }
}

// ---------------------------------------------------------------------------
// Launch: inputs in metadata order: spectrogram, W_ih, W_hh, b_ih, b_hh
// ---------------------------------------------------------------------------
extern "C" void kernel_launch(void* const* d_in, const int* in_sizes, int n_in,
                              void* d_out, int out_size)
{
    const float* spec = (const float*)d_in[0];
    const float* W_ih = (const float*)d_in[1];
    const float* W_hh = (const float*)d_in[2];
    const float* b_ih = (const float*)d_in[3];
    const float* b_hh = (const float*)d_in[4];
    float* out = (float*)d_out;

    gemm_xproj_kernel<<<T_STEPS / 64, 256>>>(spec, W_ih, b_ih, b_hh);
    lstm_seq_kernel<<<1, 256>>>(W_hh, out);
}